// round 16
// baseline (speedup 1.0000x reference)
#include <cuda_runtime.h>
#include <cooperative_groups.h>
#include <math.h>

namespace cg = cooperative_groups;

#define B_TOTAL 32768
#define X_DIM   30
#define Y_DIM   30
#define F_DIM   6
#define CELLS   (X_DIM * Y_DIM)      // 900
#define THREADS 256
#define GRID    450                  // 450 blocks * 2 halves = 900 cells
#define ELEMS_PER_BLK 73             // 450 * 73 = 32850 >= 32768

__device__ float g_S[CELLS];

__global__ void __launch_bounds__(THREADS)
fused_coop_kernel(const float* __restrict__ phi,
                  const float* __restrict__ succ,
                  const float* __restrict__ w,
                  float* __restrict__ out) {
    const int tid = threadIdx.x;
    const int bid = blockIdx.x;

    const float w0 = __ldg(&w[0]), w1 = __ldg(&w[1]), w2 = __ldg(&w[2]);
    const float w3 = __ldg(&w[3]), w4 = __ldg(&w[4]), w5 = __ldg(&w[5]);

    // ---------- PRODUCER LOADS FIRST: succ is on the barrier-critical path ----------
    const int h    = tid >> 7;        // half-block id (0/1)
    const int p    = tid & 127;       // policy index
    const int lane = tid & 31;
    const int w4g  = (tid >> 5) & 3;  // warp within half
    const int cell = bid * 2 + h;     // 0..899 exactly

    // byte offset = p*21600 + cell*24 : multiple of 8 -> float2 loads
    const float2* sbase =
        (const float2*)(succ + (size_t)p * (CELLS * F_DIM) + (size_t)cell * F_DIM);
    const float2 s0 = sbase[0], s1 = sbase[1], s2 = sbase[2];

    // ---------- Consumer preload: 73 contiguous elems per block ----------
    const int idx = bid * ELEMS_PER_BLK + tid;
    const bool is_cons = (tid < ELEMS_PER_BLK) && (idx < B_TOTAL);

    float pr0 = 0.f, pr1 = 0.f;
    int is0 = 0, ie0 = 0, is1 = 0, ie1 = 0;
    if (is_cons) {
        const float4* ph = (const float4*)(phi + (size_t)idx * 20);
        const float4 a0 = ph[0];
        const float4 a1 = ph[1];
        const float4 a2 = ph[2];
        const float4 a3 = ph[3];
        const float4 a4 = ph[4];

        pr0 = a0.x*w0 + a0.y*w1 + a0.z*w2 + a0.w*w3 + a1.x*w4 + a1.y*w5;
        pr1 = a2.z*w0 + a2.w*w1 + a3.x*w2 + a3.y*w3 + a3.z*w4 + a3.w*w5;

        is0 = (int)a1.z * Y_DIM + (int)a1.w;
        ie0 = (int)a2.x * Y_DIM + (int)a2.y;
        is1 = (int)a4.x * Y_DIM + (int)a4.y;
        ie1 = (int)a4.z * Y_DIM + (int)a4.w;
    }

    // ---------- Producer compute: one cell per 128-thread half ----------
    {
        __shared__ float smax[2][4];
        __shared__ float ssum[2][4][2];

        const float v = s0.x*w0 + s0.y*w1 + s1.x*w2 + s1.y*w3 + s2.x*w4 + s2.y*w5;
        const float x = v / 0.001f;       // match vs / T

        float mm = x;
#pragma unroll
        for (int s = 16; s > 0; s >>= 1)
            mm = fmaxf(mm, __shfl_xor_sync(0xFFFFFFFFu, mm, s));
        if (lane == 0) smax[h][w4g] = mm;
        __syncthreads();

        const float mx = fmaxf(fmaxf(smax[h][0], smax[h][1]),
                               fmaxf(smax[h][2], smax[h][3]));
        float e  = __expf(x - mx);
        float ev = e * v;
#pragma unroll
        for (int s = 16; s > 0; s >>= 1) {
            e  += __shfl_xor_sync(0xFFFFFFFFu, e,  s);
            ev += __shfl_xor_sync(0xFFFFFFFFu, ev, s);
        }
        if (lane == 0) { ssum[h][w4g][0] = e; ssum[h][w4g][1] = ev; }
        __syncthreads();

        if (p == 0) {
            const float se  = ssum[h][0][0] + ssum[h][1][0]
                            + ssum[h][2][0] + ssum[h][3][0];
            const float sev = ssum[h][0][1] + ssum[h][1][1]
                            + ssum[h][2][1] + ssum[h][3][1];
            g_S[cell] = sev / se;
        }
    }

    // ---------- Device-wide barrier (phi loads may still be in flight; fine) ----------
    cg::this_grid().sync();

    // ---------- Consumer finish ----------
    if (is_cons) {
        const float d0 = pr0 + (g_S[ie0] - g_S[is0]);
        const float d1 = pr1 + (g_S[ie1] - g_S[is1]);

        const float diff = d0 - d1;
        float2 r;
        r.x = 1.0f / (1.0f + __expf(-diff));
        r.y = 1.0f - r.x;                 // sigmoid(-x) == 1 - sigmoid(x)
        ((float2*)out)[idx] = r;
    }
}

extern "C" void kernel_launch(void* const* d_in, const int* in_sizes, int n_in,
                              void* d_out, int out_size) {
    const float* phi  = (const float*)d_in[0];   // (32768, 2, 10)
    const float* succ = (const float*)d_in[1];   // (128, 30, 30, 6)
    const float* w    = (const float*)d_in[2];   // (6,)
    float* out = (float*)d_out;                  // (32768, 2, 1)

    cudaLaunchConfig_t cfg = {};
    cfg.gridDim  = dim3(GRID);
    cfg.blockDim = dim3(THREADS);
    cfg.dynamicSmemBytes = 0;
    cfg.stream = 0;

    cudaLaunchAttribute attrs[1];
    attrs[0].id = cudaLaunchAttributeCooperative;
    attrs[0].val.cooperative = 1;
    cfg.attrs = attrs;
    cfg.numAttrs = 1;

    cudaLaunchKernelEx(&cfg, fused_coop_kernel, phi, succ, w, out);
}

// round 17
// speedup vs baseline: 1.0443x; 1.0443x over previous
#include <cuda_runtime.h>
#include <cooperative_groups.h>
#include <math.h>

namespace cg = cooperative_groups;

#define B_TOTAL 32768
#define X_DIM   30
#define Y_DIM   30
#define F_DIM   6
#define CELLS   (X_DIM * Y_DIM)      // 900
#define THREADS 256
#define GRID    450                  // 450 blocks * 2 producer warps = 900 cells
#define ELEMS_PER_BLK 73             // 450 * 73 = 32850 >= 32768

__device__ float g_S[CELLS];

__global__ void __launch_bounds__(THREADS)
fused_coop_kernel(const float* __restrict__ phi,
                  const float* __restrict__ succ,
                  const float* __restrict__ w,
                  float* __restrict__ out) {
    const int tid  = threadIdx.x;
    const int bid  = blockIdx.x;
    const int wid  = tid >> 5;
    const int lane = tid & 31;

    const float w0 = __ldg(&w[0]), w1 = __ldg(&w[1]), w2 = __ldg(&w[2]);
    const float w3 = __ldg(&w[3]), w4 = __ldg(&w[4]), w5 = __ldg(&w[5]);

    // ---------- Consumer preload (threads 0..72): phi loads first ----------
    const int idx = bid * ELEMS_PER_BLK + tid;
    const bool is_cons = (tid < ELEMS_PER_BLK) && (idx < B_TOTAL);

    float pr0 = 0.f, pr1 = 0.f;
    int is0 = 0, ie0 = 0, is1 = 0, ie1 = 0;
    if (is_cons) {
        const float4* ph = (const float4*)(phi + (size_t)idx * 20);
        const float4 a0 = ph[0];
        const float4 a1 = ph[1];
        const float4 a2 = ph[2];
        const float4 a3 = ph[3];
        const float4 a4 = ph[4];

        pr0 = a0.x*w0 + a0.y*w1 + a0.z*w2 + a0.w*w3 + a1.x*w4 + a1.y*w5;
        pr1 = a2.z*w0 + a2.w*w1 + a3.x*w2 + a3.y*w3 + a3.z*w4 + a3.w*w5;

        is0 = (int)a1.z * Y_DIM + (int)a1.w;
        ie0 = (int)a2.x * Y_DIM + (int)a2.y;
        is1 = (int)a4.x * Y_DIM + (int)a4.y;
        ie1 = (int)a4.z * Y_DIM + (int)a4.w;
    }

    // ---------- Producer: warps 6-7 only; ONE warp per cell, sync-free ----------
    if (wid >= 6) {
        const int cell = bid * 2 + (wid - 6);   // 0..899 exactly

        // Each lane covers 4 policies: lane, lane+32, lane+64, lane+96.
        // Row byte offset = p*21600 + cell*24 : 8-aligned -> float2 loads.
        float v[4];
#pragma unroll
        for (int k = 0; k < 4; ++k) {
            const int p = lane + k * 32;
            const float2* r =
                (const float2*)(succ + (size_t)p * (CELLS * F_DIM) + (size_t)cell * F_DIM);
            const float2 s0 = r[0], s1 = r[1], s2 = r[2];
            v[k] = s0.x*w0 + s0.y*w1 + s1.x*w2 + s1.y*w3 + s2.x*w4 + s2.y*w5;
        }

        float x[4];
#pragma unroll
        for (int k = 0; k < 4; ++k) x[k] = v[k] / 0.001f;   // match vs / T

        // lane-local max of 4, then warp shuffle max -> full 128-policy max
        float mm = fmaxf(fmaxf(x[0], x[1]), fmaxf(x[2], x[3]));
#pragma unroll
        for (int s = 16; s > 0; s >>= 1)
            mm = fmaxf(mm, __shfl_xor_sync(0xFFFFFFFFu, mm, s));

        float se = 0.f, sev = 0.f;
#pragma unroll
        for (int k = 0; k < 4; ++k) {
            const float e = __expf(x[k] - mm);
            se  += e;
            sev += e * v[k];
        }
#pragma unroll
        for (int s = 16; s > 0; s >>= 1) {
            se  += __shfl_xor_sync(0xFFFFFFFFu, se,  s);
            sev += __shfl_xor_sync(0xFFFFFFFFu, sev, s);
        }

        if (lane == 0) g_S[cell] = sev / se;
    }

    // ---------- Device-wide barrier ----------
    cg::this_grid().sync();

    // ---------- Consumer finish ----------
    if (is_cons) {
        const float d0 = pr0 + (g_S[ie0] - g_S[is0]);
        const float d1 = pr1 + (g_S[ie1] - g_S[is1]);

        const float diff = d0 - d1;
        float2 r;
        r.x = 1.0f / (1.0f + __expf(-diff));
        r.y = 1.0f - r.x;                 // sigmoid(-x) == 1 - sigmoid(x)
        ((float2*)out)[idx] = r;
    }
}

extern "C" void kernel_launch(void* const* d_in, const int* in_sizes, int n_in,
                              void* d_out, int out_size) {
    const float* phi  = (const float*)d_in[0];   // (32768, 2, 10)
    const float* succ = (const float*)d_in[1];   // (128, 30, 30, 6)
    const float* w    = (const float*)d_in[2];   // (6,)
    float* out = (float*)d_out;                  // (32768, 2, 1)

    cudaLaunchConfig_t cfg = {};
    cfg.gridDim  = dim3(GRID);
    cfg.blockDim = dim3(THREADS);
    cfg.dynamicSmemBytes = 0;
    cfg.stream = 0;

    cudaLaunchAttribute attrs[1];
    attrs[0].id = cudaLaunchAttributeCooperative;
    attrs[0].val.cooperative = 1;
    cfg.attrs = attrs;
    cfg.numAttrs = 1;

    cudaLaunchKernelEx(&cfg, fused_coop_kernel, phi, succ, w, out);
}